// round 10
// baseline (speedup 1.0000x reference)
#include <cuda_runtime.h>
#include <cuda_fp16.h>
#include <cstdint>
#include <cstddef>

#define S_LEN 512

// fp16 weights, full-k octet layout: addr = (i*128 + j)*8 + e, k = i*8 + e.
// 64-k mats: i<8 (8192 halves); 128-k mats: i<16 (16384 halves).
#define OFF_WIN0S 0
#define OFF_WG0S  8192
#define OFF_WG0H  16384
#define OFF_WREC0 32768
#define OFF_WIN1  49152
#define OFF_WG1X  65536
#define OFF_WG1H  81920
#define OFF_WREC1 98304
#define WH_TOTAL  114688

__device__ __align__(16) __half g_Wh[WH_TOTAL];
// ctx mats fp32, k-quad layout: addr = kq*512 + j*4 + e
__device__ __align__(16) float g_Wc[2 * 4096];

// group-internal named barrier (ids 1/2; id 0 reserved for __syncthreads)
#define GBAR(id) asm volatile("bar.sync %0, 128;" ::"r"(id) : "memory")

// ---------------- packed fp32x2 helpers (SASS FFMA2, PTX-only) ----------------
__device__ __forceinline__ unsigned long long ffma2(unsigned long long a,
                                                    unsigned long long b,
                                                    unsigned long long c) {
    unsigned long long d;
    asm("fma.rn.f32x2 %0, %1, %2, %3;" : "=l"(d) : "l"(a), "l"(b), "l"(c));
    return d;
}
__device__ __forceinline__ float redu2(unsigned long long v) {
    float lo, hi;
    asm("mov.b64 {%0, %1}, %2;" : "=f"(lo), "=f"(hi) : "l"(v));
    return lo + hi;
}
__device__ __forceinline__ unsigned long long h2pack(unsigned int u) {
    __half2 h = *reinterpret_cast<const __half2*>(&u);
    float2 f = __half22float2(h);
    unsigned long long r;
    asm("mov.b64 %0, {%1, %2};" : "=l"(r) : "f"(f.x), "f"(f.y));
    return r;
}
__device__ __forceinline__ float sigm(float x) {
    return __fdividef(1.0f, 1.0f + __expf(-x));
}
__device__ __forceinline__ float fast_tanh(float x) {
    float ax = fabsf(x);
    float e = __expf(ax + ax);
    float t = 1.0f - __fdividef(2.0f, e + 1.0f);
    return copysignf(t, x);
}
// gate = sigmoid(tanh(z)); sigmoid of t in [-1,1] via degree-7 odd polynomial
__device__ __forceinline__ float gate_fn(float z) {
    float t = fast_tanh(z);
    float t2 = t * t;
    float p = fmaf(t2, -2.00134e-4f, 2.0833333e-3f);
    p = fmaf(t2, p, -2.0833334e-2f);
    p = fmaf(t2, p, 0.25f);
    return fmaf(t, p, 0.5f);
}

// ---------------- weight layout prep ----------------
__global__ void __launch_bounds__(256) prep_weights(
    const float* __restrict__ Win0, const float* __restrict__ Wg0,
    const float* __restrict__ Wrec0, const float* __restrict__ Win1,
    const float* __restrict__ Wrec1, const float* __restrict__ Wg1) {
    int idx = blockIdx.x * 256 + threadIdx.x;
    if (idx < 16384) {  // 64-k mats: Win0 seq / Wg0 seq
        int m = idx >> 13;
        int a = idx & 8191;
        int e = a & 7, t = a >> 3;
        int j = t & 127, i = t >> 7;
        int k = i * 8 + e;
        float v = m ? Wg0[j * 224 + k] : Win0[j * 96 + k];
        g_Wh[idx] = __float2half_rn(v);
    } else if (idx < WH_TOTAL) {  // 128-k mats
        int m = (idx - 16384) >> 14;
        int a = (idx - 16384) & 16383;
        int e = a & 7, t = a >> 3;
        int j = t & 127, i = t >> 7;
        int k = i * 8 + e;
        float v;
        switch (m) {
            case 0: v = Wg0[j * 224 + 96 + k]; break;
            case 1: v = Wrec0[j * 128 + k]; break;
            case 2: v = Win1[j * 128 + k]; break;
            case 3: v = Wg1[j * 256 + k]; break;
            case 4: v = Wg1[j * 256 + 128 + k]; break;
            default: v = Wrec1[j * 128 + k]; break;
        }
        g_Wh[idx] = __float2half_rn(v);
    } else if (idx < WH_TOTAL + 8192) {  // ctx parts, fp32 k-quad
        int r = idx - WH_TOTAL;
        int m = r >> 12;
        int a = r & 4095;
        int j = (a >> 2) & 127;
        int k = ((a >> 9) << 2) | (a & 3);
        g_Wc[r] = m ? Wg0[j * 224 + 64 + k] : Win0[j * 96 + 64 + k];
    }
}

// Full-k dual mat-vec for row j over 4 batches, fp16 weights. No cross-lane
// reduction (thread owns the full dot). x: smem [4][XS], broadcast reads.
template <int ITERS, int XS>
__device__ __forceinline__ void dualmv4(const __half* __restrict__ Wa,
                                        const __half* __restrict__ Wb,
                                        const float* __restrict__ x,
                                        float ra[4], float rb[4]) {
    unsigned long long a[4] = {0, 0, 0, 0};
    unsigned long long c[4] = {0, 0, 0, 0};
#pragma unroll
    for (int i = 0; i < ITERS; ++i) {
        uint4 wra = __ldg(reinterpret_cast<const uint4*>(Wa + (size_t)i * 1024));
        uint4 wrb = __ldg(reinterpret_cast<const uint4*>(Wb + (size_t)i * 1024));
        unsigned long long wa0 = h2pack(wra.x), wa1 = h2pack(wra.y);
        unsigned long long wa2 = h2pack(wra.z), wa3 = h2pack(wra.w);
        unsigned long long wb0 = h2pack(wrb.x), wb1 = h2pack(wrb.y);
        unsigned long long wb2 = h2pack(wrb.z), wb3 = h2pack(wrb.w);
#pragma unroll
        for (int b = 0; b < 4; ++b) {
            ulonglong2 x0 = *reinterpret_cast<const ulonglong2*>(x + b * XS + i * 8);
            ulonglong2 x1 = *reinterpret_cast<const ulonglong2*>(x + b * XS + i * 8 + 4);
            a[b] = ffma2(wa0, x0.x, a[b]);
            a[b] = ffma2(wa1, x0.y, a[b]);
            a[b] = ffma2(wa2, x1.x, a[b]);
            a[b] = ffma2(wa3, x1.y, a[b]);
            c[b] = ffma2(wb0, x0.x, c[b]);
            c[b] = ffma2(wb1, x0.y, c[b]);
            c[b] = ffma2(wb2, x1.x, c[b]);
            c[b] = ffma2(wb3, x1.y, c[b]);
        }
    }
#pragma unroll
    for (int b = 0; b < 4; ++b) {
        ra[b] = redu2(a[b]);
        rb[b] = redu2(c[b]);
    }
}

// RK4 for one cell executed by ONE 128-thread group (named barrier BARID).
// hh[2][512] ping-pongs via cu; on entry hh[cu] holds the group's current h
// (all 128 rows, 4 batches); on exit hh[cu] holds the new h and hst[] the
// thread's 4 owned (row j, batch b) values.
template <int BARID>
__device__ __forceinline__ void rk4_group(const __half* __restrict__ Wg,
                                          const __half* __restrict__ Wr, float itau,
                                          const float* xin, const float* xg,
                                          float* hst, float (*hh)[512], int& cu,
                                          int j) {
    float ka[4] = {0.f, 0.f, 0.f, 0.f};
    float ht[4] = {hst[0], hst[1], hst[2], hst[3]};
#pragma unroll
    for (int sub = 0; sub < 4; ++sub) {
        float ra[4], rb[4];
        dualmv4<16, 128>(Wg, Wr, hh[cu], ra, rb);
        const float kw = (sub == 0 || sub == 3) ? 1.0f : 2.0f;
        const float cv = (sub < 2) ? 0.5f : 1.0f;
#pragma unroll
        for (int b = 0; b < 4; ++b) {
            float gate = gate_fn(ra[b] + xg[b]);
            float kv = fmaf(gate, rb[b], fmaf(-ht[b], itau, xin[b]));
            ka[b] = fmaf(kw, kv, ka[b]);
            float nh = (sub < 3) ? fmaf(cv, kv, hst[b])
                                 : fast_tanh(fmaf(ka[b], 0.16666667f, hst[b]));
            ht[b] = nh;
            hh[cu ^ 1][b * 128 + j] = nh;
        }
        GBAR(BARID);
        cu ^= 1;
    }
    hst[0] = ht[0];
    hst[1] = ht[1];
    hst[2] = ht[2];
    hst[3] = ht[3];
}

// ---------------- persistent recurrence: 128 CTAs x 256 threads ----------------
// Software pipeline across the two cells: group A (tid<128) runs the cell-0
// chain, group B (tid>=128) runs the cell-1 chain one step behind, consuming
// h0 via a parity double-buffer. One CTA barrier per step couples them.
__global__ void __launch_bounds__(256, 1)
ltc_recurrent(const float* __restrict__ seq, const float* __restrict__ ctx,
              const float* __restrict__ tau0, const float* __restrict__ bg0,
              const float* __restrict__ tau1, const float* __restrict__ bg1,
              const float* __restrict__ W1, const float* __restrict__ b1,
              const float* __restrict__ W2, const float* __restrict__ b2,
              float* __restrict__ out) {
    __shared__ __align__(16) float hhA[2][512];   // cell-0 RK4 ping-pong
    __shared__ __align__(16) float hhB[2][512];   // cell-1 RK4 ping-pong
    __shared__ __align__(16) float h0buf[2][512]; // A->B handoff, parity-indexed
    __shared__ __align__(16) float xsA[4 * 64];   // step's x slice (group A)
    __shared__ __align__(16) float xc[4 * 32];    // ctx
    __shared__ __align__(16) float st0[512];      // final h1 for classifier
    const int tid = threadIdx.x;
    const bool isA = tid < 128;
    const int j = tid & 127;
    const int b0g = blockIdx.x * 4;

    // group-specific weight pointers / params
    const int wo = j * 8;
    const __half* Wp0 = g_Wh + (isA ? OFF_WIN0S : OFF_WIN1) + wo;  // proj mat a
    const __half* Wp1 = g_Wh + (isA ? OFF_WG0S : OFF_WG1X) + wo;   // proj mat b
    const __half* Wc0 = g_Wh + (isA ? OFF_WG0H : OFF_WG1H) + wo;   // gate mat
    const __half* Wc1 = g_Wh + (isA ? OFF_WREC0 : OFF_WREC1) + wo; // rec mat
    const float taup = isA ? tau0[j] : tau1[j];
    const float itau = __fdividef(1.0f, log1pf(__expf(taup)) + 1.0f);
    const float bgj = isA ? 0.0f : bg1[j];

    // per-A-thread x element pair: idx = 2j -> batch j>>5, feature (2j)&63
    const int xb = j >> 5;
    const int xk = (2 * j) & 63;
    const float* seqp = seq + ((size_t)(b0g + xb) * S_LEN) * 64 + xk;

    // ---- step-invariant ctx projection (group A, fp32 k-quad) ----
    if (isA) {
        int b = j >> 5, i = j & 31;
        xc[b * 32 + i] = ctx[(size_t)(b0g + b) * 32 + i];
    }
    __syncthreads();
    float xinc[4] = {0.f, 0.f, 0.f, 0.f}, xgc[4] = {0.f, 0.f, 0.f, 0.f};
    if (isA) {
        const float* Wa = g_Wc + j * 4;
        const float* Wb = g_Wc + 4096 + j * 4;
        unsigned long long a[4] = {0, 0, 0, 0}, c[4] = {0, 0, 0, 0};
#pragma unroll
        for (int kq = 0; kq < 8; ++kq) {
            ulonglong2 wa = __ldg(reinterpret_cast<const ulonglong2*>(Wa + kq * 512));
            ulonglong2 wb = __ldg(reinterpret_cast<const ulonglong2*>(Wb + kq * 512));
#pragma unroll
            for (int b = 0; b < 4; ++b) {
                ulonglong2 xv = *reinterpret_cast<const ulonglong2*>(xc + b * 32 + kq * 4);
                a[b] = ffma2(wa.x, xv.x, a[b]);
                a[b] = ffma2(wa.y, xv.y, a[b]);
                c[b] = ffma2(wb.x, xv.x, c[b]);
                c[b] = ffma2(wb.y, xv.y, c[b]);
            }
        }
        const float bg0j = bg0[j];
#pragma unroll
        for (int b = 0; b < 4; ++b) {
            xinc[b] = redu2(a[b]);
            xgc[b] = redu2(c[b]) + bg0j;
        }
    }

    float hst[4] = {0.f, 0.f, 0.f, 0.f};  // A: h0 state; B: h1 state (row j, 4 b)
    int cuA = 0, cuB = 0;
    if (isA) {
#pragma unroll
        for (int b = 0; b < 4; ++b) hhA[0][b * 128 + j] = 0.f;
    } else {
#pragma unroll
        for (int b = 0; b < 4; ++b) hhB[0][b * 128 + j] = 0.f;
    }
    __syncthreads();

    for (int s = 0; s <= S_LEN; ++s) {
        if (isA) {
            if (s < S_LEN) {
                // stage x(s)
                *reinterpret_cast<float2*>(xsA + 2 * j) =
                    *reinterpret_cast<const float2*>(seqp + (size_t)s * 64);
                GBAR(1);
                // cell-0 input projections (seq part) + ctx base
                float xin[4], xg[4];
                dualmv4<8, 64>(Wp0, Wp1, xsA, xin, xg);
#pragma unroll
                for (int b = 0; b < 4; ++b) { xin[b] += xinc[b]; xg[b] += xgc[b]; }
                // cell-0 RK4 (hhA[cuA] holds h0; leaves h0_new there + in hst)
                rk4_group<1>(Wc0, Wc1, itau, xin, xg, hst, hhA, cuA, j);
                // publish h0(s) for group B (read after the CTA bar)
#pragma unroll
                for (int b = 0; b < 4; ++b) h0buf[s & 1][b * 128 + j] = hst[b];
            }
        } else {
            if (s > 0) {
                // cell-1 input projections from h0(s-1)
                float xin[4], xg[4];
                dualmv4<16, 128>(Wp0, Wp1, h0buf[(s - 1) & 1], xin, xg);
#pragma unroll
                for (int b = 0; b < 4; ++b) xg[b] += bgj;
                // cell-1 RK4
                rk4_group<2>(Wc0, Wc1, itau, xin, xg, hst, hhB, cuB, j);
            }
        }
        __syncthreads();
    }

    // ---- classifier: sigmoid(relu(h1 @ W1^T + b1) @ W2^T + b2) ----
    if (!isA) {
#pragma unroll
        for (int b = 0; b < 4; ++b) st0[b * 128 + j] = hst[b];
    }
    __syncthreads();
    if (tid < 128) {
        const int b = tid >> 5, ln = tid & 31;
        float a0 = b1[ln], a1 = b1[ln + 32];
        const float* hv = st0 + b * 128;
        const float* w0 = W1 + ln * 128;
        const float* w1 = W1 + (ln + 32) * 128;
#pragma unroll 8
        for (int k = 0; k < 128; ++k) {
            float h = hv[k];
            a0 = fmaf(h, w0[k], a0);
            a1 = fmaf(h, w1[k], a1);
        }
        a0 = fmaxf(a0, 0.f);
        a1 = fmaxf(a1, 0.f);
        float pr = a0 * __ldg(W2 + ln) + a1 * __ldg(W2 + ln + 32);
#pragma unroll
        for (int off = 16; off; off >>= 1) pr += __shfl_xor_sync(0xffffffffu, pr, off);
        if (ln == 0) out[b0g + b] = sigm(pr + b2[0]);
    }
}

extern "C" void kernel_launch(void* const* d_in, const int* in_sizes, int n_in,
                              void* d_out, int out_size) {
    const float* seq   = (const float*)d_in[0];
    const float* ctx   = (const float*)d_in[1];
    const float* tau0  = (const float*)d_in[2];
    const float* Win0  = (const float*)d_in[3];
    const float* Wrec0 = (const float*)d_in[4];
    const float* Wg0   = (const float*)d_in[5];
    const float* bg0   = (const float*)d_in[6];
    const float* tau1  = (const float*)d_in[7];
    const float* Win1  = (const float*)d_in[8];
    const float* Wrec1 = (const float*)d_in[9];
    const float* Wg1   = (const float*)d_in[10];
    const float* bg1   = (const float*)d_in[11];
    const float* W1    = (const float*)d_in[12];
    const float* b1    = (const float*)d_in[13];
    const float* W2    = (const float*)d_in[14];
    const float* b2    = (const float*)d_in[15];
    float* out = (float*)d_out;

    prep_weights<<<(WH_TOTAL + 8192 + 255) / 256, 256>>>(Win0, Wg0, Wrec0, Win1,
                                                         Wrec1, Wg1);
    ltc_recurrent<<<128, 256>>>(seq, ctx, tau0, bg0, tau1, bg1, W1, b1, W2, b2, out);
}

// round 11
// speedup vs baseline: 1.8591x; 1.8591x over previous
#include <cuda_runtime.h>
#include <cuda_fp16.h>
#include <cstdint>
#include <cstddef>

#define S_LEN 512
#define HSTRIDE 128
#define XSTRIDE 64

// fp16 weight offsets (half elements). Layout (both mat widths):
// addr = OFF + i*2048 + half*1024 + j*8 + e ;  k = half*K/2 + i*8 + e
#define OFF_WIN0S 0
#define OFF_WG0S  8192
#define OFF_WG0H  16384
#define OFF_WREC0 32768
#define OFF_WIN1  49152
#define OFF_WG1X  65536
#define OFF_WG1H  81920
#define OFF_WREC1 98304
#define WH_TOTAL  114688

__device__ __align__(16) __half g_Wh[WH_TOTAL];
// ctx mats fp32, k-quad layout: addr = kq*512 + j*4 + e
__device__ __align__(16) float g_Wc[2 * 4096];

// ---------------- packed fp32x2 helpers (SASS FFMA2, PTX-only) ----------------
__device__ __forceinline__ unsigned long long ffma2(unsigned long long a,
                                                    unsigned long long b,
                                                    unsigned long long c) {
    unsigned long long d;
    asm("fma.rn.f32x2 %0, %1, %2, %3;" : "=l"(d) : "l"(a), "l"(b), "l"(c));
    return d;
}
__device__ __forceinline__ float redu2(unsigned long long v) {
    float lo, hi;
    asm("mov.b64 {%0, %1}, %2;" : "=f"(lo), "=f"(hi) : "l"(v));
    return lo + hi;
}
__device__ __forceinline__ unsigned long long h2pack(unsigned int u) {
    __half2 h = *reinterpret_cast<const __half2*>(&u);
    float2 f = __half22float2(h);
    unsigned long long r;
    asm("mov.b64 %0, {%1, %2};" : "=l"(r) : "f"(f.x), "f"(f.y));
    return r;
}
__device__ __forceinline__ float sigm(float x) {
    return __fdividef(1.0f, 1.0f + __expf(-x));
}
__device__ __forceinline__ float fast_tanh(float x) {
    float ax = fabsf(x);
    float e = __expf(ax + ax);
    float t = 1.0f - __fdividef(2.0f, e + 1.0f);
    return copysignf(t, x);
}
// gate = sigmoid(tanh(z)); sigmoid of t in [-1,1] via degree-7 odd polynomial
__device__ __forceinline__ float gate_fn(float z) {
    float t = fast_tanh(z);
    float t2 = t * t;
    float p = fmaf(t2, -2.00134e-4f, 2.0833333e-3f);
    p = fmaf(t2, p, -2.0833334e-2f);
    p = fmaf(t2, p, 0.25f);
    return fmaf(t, p, 0.5f);
}
// Combine k-half partials across lanes l, l^16; own[bb] = full dot for batch
// 2*half+bb. 2 shfl per accumulator group.
__device__ __forceinline__ void combine_own(const unsigned long long a[4], int half,
                                            float own[2]) {
#pragma unroll
    for (int bb = 0; bb < 2; ++bb) {
        float mine = redu2(half ? a[2 + bb] : a[bb]);
        float send = redu2(half ? a[bb] : a[2 + bb]);
        float recv = __shfl_xor_sync(0xffffffffu, send, 16);
        own[bb] = mine + recv;
    }
}

// ---------------- weight layout prep ----------------
__global__ void __launch_bounds__(256) prep_weights(
    const float* __restrict__ Win0, const float* __restrict__ Wg0,
    const float* __restrict__ Wrec0, const float* __restrict__ Win1,
    const float* __restrict__ Wrec1, const float* __restrict__ Wg1) {
    int idx = blockIdx.x * 256 + threadIdx.x;
    if (idx < 16384) {  // 64-k mats: Win0 seq / Wg0 seq
        int m = idx >> 13;
        int a = idx & 8191;
        int e = a & 7, t = a >> 3;
        int j = t & 127, t2 = t >> 7;
        int hf = t2 & 1, i = t2 >> 1;
        int k = hf * 32 + i * 8 + e;
        float v = m ? Wg0[j * 224 + k] : Win0[j * 96 + k];
        g_Wh[idx] = __float2half_rn(v);
    } else if (idx < WH_TOTAL) {  // 128-k mats
        int m = (idx - 16384) >> 14;
        int a = (idx - 16384) & 16383;
        int e = a & 7, t = a >> 3;
        int j = t & 127, t2 = t >> 7;
        int hf = t2 & 1, i = t2 >> 1;
        int k = hf * 64 + i * 8 + e;
        float v;
        switch (m) {
            case 0: v = Wg0[j * 224 + 96 + k]; break;
            case 1: v = Wrec0[j * 128 + k]; break;
            case 2: v = Win1[j * 128 + k]; break;
            case 3: v = Wg1[j * 256 + k]; break;
            case 4: v = Wg1[j * 256 + 128 + k]; break;
            default: v = Wrec1[j * 128 + k]; break;
        }
        g_Wh[idx] = __float2half_rn(v);
    } else if (idx < WH_TOTAL + 8192) {  // ctx parts, fp32 k-quad
        int r = idx - WH_TOTAL;
        int m = r >> 12;
        int a = r & 4095;
        int j = (a >> 2) & 127;
        int k = ((a >> 9) << 2) | (a & 3);
        g_Wc[r] = m ? Wg0[j * 224 + 64 + k] : Win0[j * 96 + 64 + k];
    }
}

// Half-split dual mat-vec, fp16 weights; mat offsets are COMPILE-TIME so SASS
// uses one base register + LDG immediate offsets. Returns full dots for this
// lane's two owned batches. ITERS = (k/2)/8.
template <int ITERS, int XS, int OFFA, int OFFB>
__device__ __forceinline__ void dualmv_own(const __half* __restrict__ wbase,
                                           const float* __restrict__ x, int half,
                                           float ra[2], float rb[2]) {
    unsigned long long a[4] = {0, 0, 0, 0};
    unsigned long long c[4] = {0, 0, 0, 0};
#pragma unroll
    for (int i = 0; i < ITERS; ++i) {
        uint4 wra = __ldg(reinterpret_cast<const uint4*>(wbase + OFFA + i * 2048));
        uint4 wrb = __ldg(reinterpret_cast<const uint4*>(wbase + OFFB + i * 2048));
        unsigned long long wa0 = h2pack(wra.x), wa1 = h2pack(wra.y);
        unsigned long long wa2 = h2pack(wra.z), wa3 = h2pack(wra.w);
        unsigned long long wb0 = h2pack(wrb.x), wb1 = h2pack(wrb.y);
        unsigned long long wb2 = h2pack(wrb.z), wb3 = h2pack(wrb.w);
#pragma unroll
        for (int b = 0; b < 4; ++b) {
            ulonglong2 x0 = *reinterpret_cast<const ulonglong2*>(x + b * XS + i * 16);
            ulonglong2 x1 = *reinterpret_cast<const ulonglong2*>(x + b * XS + i * 16 + 4);
            a[b] = ffma2(wa0, x0.x, a[b]);
            a[b] = ffma2(wa1, x0.y, a[b]);
            a[b] = ffma2(wa2, x1.x, a[b]);
            a[b] = ffma2(wa3, x1.y, a[b]);
            c[b] = ffma2(wb0, x0.x, c[b]);
            c[b] = ffma2(wb1, x0.y, c[b]);
            c[b] = ffma2(wb2, x1.x, c[b]);
            c[b] = ffma2(wb3, x1.y, c[b]);
        }
    }
    combine_own(a, half, ra);
    combine_own(c, half, rb);
}

// RK4 for one cell on its own persistent ping-pong pair hh[2][512]. On entry
// hh[cu] holds h; on exit hh[cu] holds h_new (cu net-unchanged: 4 flips) and
// hst[] the thread's 2 owned (row, batch) values. One CTA bar per sub-phase.
template <int OFFG, int OFFR>
__device__ __forceinline__ void rk4_cell(const __half* __restrict__ wbase, float itau,
                                         const float* xin, const float* xg, float* hst,
                                         float (*hh)[512], int& cu, int xoff,
                                         int hslot, int half) {
    float ka[2] = {0.f, 0.f};
    float ht[2] = {hst[0], hst[1]};
#pragma unroll
    for (int sub = 0; sub < 4; ++sub) {
        float ra[2], rb[2];
        dualmv_own<8, HSTRIDE, OFFG, OFFR>(wbase, hh[cu] + xoff, half, ra, rb);
        const float kw = (sub == 0 || sub == 3) ? 1.0f : 2.0f;
        const float cv = (sub < 2) ? 0.5f : 1.0f;
#pragma unroll
        for (int bb = 0; bb < 2; ++bb) {
            float gate = gate_fn(ra[bb] + xg[bb]);
            float kv = fmaf(gate, rb[bb], fmaf(-ht[bb], itau, xin[bb]));
            ka[bb] = fmaf(kw, kv, ka[bb]);
            float nh = (sub < 3) ? fmaf(cv, kv, hst[bb])
                                 : fast_tanh(fmaf(ka[bb], 0.16666667f, hst[bb]));
            ht[bb] = nh;
            hh[cu ^ 1][(2 * half + bb) * HSTRIDE + hslot] = nh;
        }
        __syncthreads();
        cu ^= 1;
    }
    hst[0] = ht[0];
    hst[1] = ht[1];
}

// ---------------- persistent recurrence: 128 CTAs x 256 threads ----------------
// Warp w covers rows jl = w*16 + (lane&15); lane half = lane>>4 covers one k-half
// in the matmuls and owns batches {2*half, 2*half+1} elementwise. Cells 0 and 1
// keep separate ping-pong buffers, so no h staging barrier is needed.
__global__ void __launch_bounds__(256, 1)
ltc_recurrent(const float* __restrict__ seq, const float* __restrict__ ctx,
              const float* __restrict__ tau0, const float* __restrict__ bg0,
              const float* __restrict__ tau1, const float* __restrict__ bg1,
              const float* __restrict__ W1, const float* __restrict__ b1,
              const float* __restrict__ W2, const float* __restrict__ b2,
              float* __restrict__ out) {
    __shared__ __align__(16) float hhA[2][512];   // cell-0 h ping-pong
    __shared__ __align__(16) float hhB[2][512];   // cell-1 h ping-pong
    __shared__ __align__(16) float xs[2][4 * XSTRIDE];  // double-buffered x
    __shared__ __align__(16) float xc[4 * 32];
    __shared__ __align__(16) float st0[512];
    __shared__ __align__(16) float st1[512];
    const int tid = threadIdx.x;
    const int lane = tid & 31;
    const int w = tid >> 5;
    const int half = lane >> 4;
    const int jl = (w << 4) + (lane & 15);
    const int xoff = half * 8;
    // smem slot of h[jl]: slot = i*16 + half_j*8 + e for jl = half_j*64+i*8+e
    const int hslot = (((jl >> 3) & 7) << 4) + ((jl >> 6) << 3) + (jl & 7);
    const int b0g = blockIdx.x * 4;

    const float it0 = __fdividef(1.0f, log1pf(__expf(tau0[jl])) + 1.0f);
    const float it1 = __fdividef(1.0f, log1pf(__expf(tau1[jl])) + 1.0f);
    const float bg1j = bg1[jl];

    // single weight base register; mat selection via LDG immediate offsets
    const __half* wbase = g_Wh + half * 1024 + jl * 8;

    // per-thread x-element: batch xb, feature xk
    const int xb = tid >> 6;
    const int xk = tid & 63;
    const int xslot = xb * XSTRIDE + ((((xk >> 3) & 3) << 4) + ((xk >> 5) << 3) + (xk & 7));
    const float* seq_elem = seq + ((size_t)(b0g + xb) * S_LEN) * 64 + xk;

    // ---- step-invariant ctx projection (threads 0-127, fp32 k-quad) ----
    if (tid < 128) {
        int b = tid >> 5, i = tid & 31;
        xc[b * 32 + i] = ctx[(size_t)(b0g + b) * 32 + i];
    }
    __syncthreads();
    if (tid < 128) {
        const int j = tid;
        const float* Wa = g_Wc + j * 4;
        const float* Wb = g_Wc + 4096 + j * 4;
        unsigned long long a[4] = {0, 0, 0, 0}, c[4] = {0, 0, 0, 0};
#pragma unroll
        for (int kq = 0; kq < 8; ++kq) {
            ulonglong2 wa = __ldg(reinterpret_cast<const ulonglong2*>(Wa + kq * 512));
            ulonglong2 wb = __ldg(reinterpret_cast<const ulonglong2*>(Wb + kq * 512));
#pragma unroll
            for (int b = 0; b < 4; ++b) {
                ulonglong2 xv = *reinterpret_cast<const ulonglong2*>(xc + b * 32 + kq * 4);
                a[b] = ffma2(wa.x, xv.x, a[b]);
                a[b] = ffma2(wa.y, xv.y, a[b]);
                c[b] = ffma2(wb.x, xv.x, c[b]);
                c[b] = ffma2(wb.y, xv.y, c[b]);
            }
        }
        const float bg0j = bg0[j];
#pragma unroll
        for (int b = 0; b < 4; ++b) {
            st0[b * 128 + j] = redu2(a[b]);
            st1[b * 128 + j] = redu2(c[b]) + bg0j;
        }
    }
    __syncthreads();
    float xinc[2], xgc[2];
#pragma unroll
    for (int bb = 0; bb < 2; ++bb) {
        xinc[bb] = st0[(2 * half + bb) * 128 + jl];
        xgc[bb] = st1[(2 * half + bb) * 128 + jl];
    }

    float h0r[2] = {0.f, 0.f}, h1r[2] = {0.f, 0.f};
    int cuA = 0, cuB = 0;
    hhA[0][tid] = 0.f;
    hhA[0][256 + tid] = 0.f;
    hhB[0][tid] = 0.f;
    hhB[0][256 + tid] = 0.f;
    xs[0][xslot] = seq_elem[0];
    __syncthreads();

    int p = 0;
    for (int s = 0; s < S_LEN; ++s) {
        // prefetch x(s+1) into a register early (hidden behind cell 0)
        float xpv = 0.f;
        if (s + 1 < S_LEN) xpv = seq_elem[(size_t)(s + 1) * 64];

        // cell-0 input projections (seq part, unbarriered) + ctx base
        float xin0[2], xg0[2];
        dualmv_own<4, XSTRIDE, OFF_WIN0S, OFF_WG0S>(wbase, xs[p] + xoff, half,
                                                    xin0, xg0);
#pragma unroll
        for (int bb = 0; bb < 2; ++bb) { xin0[bb] += xinc[bb]; xg0[bb] += xgc[bb]; }

        // cell 0 on hhA (leaves h0_new in hhA[cuA] and h0r)
        rk4_cell<OFF_WG0H, OFF_WREC0>(wbase, it0, xin0, xg0, h0r, hhA, cuA, xoff,
                                      hslot, half);

        // stage next step's x (readers are next step, after cell-1's bars)
        if (s + 1 < S_LEN) xs[p ^ 1][xslot] = xpv;

        // cell-1 input projections from h0_new (unbarriered — hhA[cuA] is
        // stable and hhB is untouched by this matvec)
        float xin1[2], xg1[2];
        dualmv_own<8, HSTRIDE, OFF_WIN1, OFF_WG1X>(wbase, hhA[cuA] + xoff, half,
                                                   xin1, xg1);
#pragma unroll
        for (int bb = 0; bb < 2; ++bb) xg1[bb] += bg1j;

        // cell 1 on hhB (h1 persists in hhB[cuB] across steps)
        rk4_cell<OFF_WG1H, OFF_WREC1>(wbase, it1, xin1, xg1, h1r, hhB, cuB, xoff,
                                      hslot, half);
        p ^= 1;
    }

    // ---- classifier: sigmoid(relu(h1 @ W1^T + b1) @ W2^T + b2) ----
    __syncthreads();
#pragma unroll
    for (int bb = 0; bb < 2; ++bb) st0[(2 * half + bb) * 128 + jl] = h1r[bb];
    __syncthreads();
    if (tid < 128) {
        const int b = tid >> 5, ln = tid & 31;
        float a0 = b1[ln], a1 = b1[ln + 32];
        const float* hv = st0 + b * 128;
        const float* w0 = W1 + ln * 128;
        const float* w1 = W1 + (ln + 32) * 128;
#pragma unroll 8
        for (int k = 0; k < 128; ++k) {
            float h = hv[k];
            a0 = fmaf(h, w0[k], a0);
            a1 = fmaf(h, w1[k], a1);
        }
        a0 = fmaxf(a0, 0.f);
        a1 = fmaxf(a1, 0.f);
        float pr = a0 * __ldg(W2 + ln) + a1 * __ldg(W2 + ln + 32);
#pragma unroll
        for (int off = 16; off; off >>= 1) pr += __shfl_xor_sync(0xffffffffu, pr, off);
        if (ln == 0) out[b0g + b] = sigm(pr + b2[0]);
    }
}

extern "C" void kernel_launch(void* const* d_in, const int* in_sizes, int n_in,
                              void* d_out, int out_size) {
    const float* seq   = (const float*)d_in[0];
    const float* ctx   = (const float*)d_in[1];
    const float* tau0  = (const float*)d_in[2];
    const float* Win0  = (const float*)d_in[3];
    const float* Wrec0 = (const float*)d_in[4];
    const float* Wg0   = (const float*)d_in[5];
    const float* bg0   = (const float*)d_in[6];
    const float* tau1  = (const float*)d_in[7];
    const float* Win1  = (const float*)d_in[8];
    const float* Wrec1 = (const float*)d_in[9];
    const float* Wg1   = (const float*)d_in[10];
    const float* bg1   = (const float*)d_in[11];
    const float* W1    = (const float*)d_in[12];
    const float* b1    = (const float*)d_in[13];
    const float* W2    = (const float*)d_in[14];
    const float* b2    = (const float*)d_in[15];
    float* out = (float*)d_out;

    prep_weights<<<(WH_TOTAL + 8192 + 255) / 256, 256>>>(Win0, Wg0, Wrec0, Win1,
                                                         Wrec1, Wg1);
    ltc_recurrent<<<128, 256>>>(seq, ctx, tau0, bg0, tau1, bg1, W1, b1, W2, b2, out);
}

// round 12
// speedup vs baseline: 3.2961x; 1.7729x over previous
#include <cuda_runtime.h>
#include <cuda_fp16.h>
#include <cstdint>
#include <cstddef>

#define S_LEN 512

// mma-fragment-linear weights (u32 lane-regs). For mat,k-tile q,n-tile t:
// u32 at base + (q*16 + t)*64 + lane*2 + r holds halves {W[j][k0], W[j][k0+1]}
// with j = t*8 + lane/4, k0 = q*16 + r*8 + 2*(lane%4).
#define MM_WG0H  0
#define MM_WREC0 8192
#define MM_WIN1  16384
#define MM_WG1X  24576
#define MM_WG1H  32768
#define MM_WREC1 40960
#define MM_WIN0S 49152
#define MM_WG0S  53248
#define MM_TOTAL 57344

__device__ __align__(16) uint32_t g_Wm[MM_TOTAL];
// ctx mats fp32 row-major [j][32]: [0]=Win0 ctx part, [4096]=Wg0 ctx part
__device__ __align__(16) float g_Wc[2 * 4096];

#define HSTB 272  // h smem row stride bytes (136 halves)
#define XSTB 144  // x smem row stride bytes (72 halves)

__device__ __forceinline__ float sigm(float x) {
    return __fdividef(1.0f, 1.0f + __expf(-x));
}
__device__ __forceinline__ float fast_tanh(float x) {
    float ax = fabsf(x);
    float e = __expf(ax + ax);
    float t = 1.0f - __fdividef(2.0f, e + 1.0f);
    return copysignf(t, x);
}
// gate = sigmoid(tanh(z)); sigmoid of t in [-1,1] via degree-7 odd polynomial
__device__ __forceinline__ float gate_fn(float z) {
    float t = fast_tanh(z);
    float t2 = t * t;
    float p = fmaf(t2, -2.00134e-4f, 2.0833333e-3f);
    p = fmaf(t2, p, -2.0833334e-2f);
    p = fmaf(t2, p, 0.25f);
    return fmaf(t, p, 0.5f);
}

// ---------------- weight prep: fragment-linear fp16 + fp32 ctx ----------------
__global__ void __launch_bounds__(256) prep_weights(
    const float* __restrict__ Win0, const float* __restrict__ Wg0,
    const float* __restrict__ Wrec0, const float* __restrict__ Win1,
    const float* __restrict__ Wrec1, const float* __restrict__ Wg1) {
    int idx = blockIdx.x * 256 + threadIdx.x;
    if (idx < MM_TOTAL) {
        int mat, rem;
        if (idx < 49152) {
            mat = idx >> 13;
            rem = idx & 8191;
        } else {
            mat = 6 + ((idx - 49152) >> 12);
            rem = (idx - 49152) & 4095;
        }
        int q = rem >> 10;
        int rr = rem & 1023;
        int t = rr >> 6;
        int le = rr & 63;
        int l = le >> 1, r = le & 1;
        int j = t * 8 + (l >> 2);
        int k = q * 16 + (r << 3) + 2 * (l & 3);
        float f0, f1;
        switch (mat) {
            case 0: f0 = Wg0[j * 224 + 96 + k]; f1 = Wg0[j * 224 + 97 + k]; break;
            case 1: f0 = Wrec0[j * 128 + k]; f1 = Wrec0[j * 128 + k + 1]; break;
            case 2: f0 = Win1[j * 128 + k]; f1 = Win1[j * 128 + k + 1]; break;
            case 3: f0 = Wg1[j * 256 + k]; f1 = Wg1[j * 256 + k + 1]; break;
            case 4: f0 = Wg1[j * 256 + 128 + k]; f1 = Wg1[j * 256 + 129 + k]; break;
            case 5: f0 = Wrec1[j * 128 + k]; f1 = Wrec1[j * 128 + k + 1]; break;
            case 6: f0 = Win0[j * 96 + k]; f1 = Win0[j * 96 + k + 1]; break;
            default: f0 = Wg0[j * 224 + k]; f1 = Wg0[j * 224 + k + 1]; break;
        }
        uint32_t u = (uint32_t)__half_as_ushort(__float2half_rn(f0)) |
                     ((uint32_t)__half_as_ushort(__float2half_rn(f1)) << 16);
        g_Wm[idx] = u;
    } else if (idx < MM_TOTAL + 8192) {
        int r2 = idx - MM_TOTAL;
        int m = r2 >> 12, a = r2 & 4095;
        int j = a >> 5, k = a & 31;
        g_Wc[r2] = m ? Wg0[j * 224 + 64 + k] : Win0[j * 96 + 64 + k];
    }
}

// ---------------- mma primitives ----------------
__device__ __forceinline__ void ldsm4(uint32_t addr, uint32_t& r0, uint32_t& r1,
                                      uint32_t& r2, uint32_t& r3) {
    asm volatile("ldmatrix.sync.aligned.m8n8.x4.shared.b16 {%0,%1,%2,%3}, [%4];"
                 : "=r"(r0), "=r"(r1), "=r"(r2), "=r"(r3)
                 : "r"(addr));
}
__device__ __forceinline__ void mma16816(float* c, uint32_t a0, uint32_t a1,
                                         uint32_t a2, uint32_t a3, uint32_t b0,
                                         uint32_t b1) {
    asm volatile(
        "mma.sync.aligned.m16n8k16.row.col.f32.f16.f16.f32 "
        "{%0,%1,%2,%3}, {%4,%5,%6,%7}, {%8,%9}, {%0,%1,%2,%3};"
        : "+f"(c[0]), "+f"(c[1]), "+f"(c[2]), "+f"(c[3])
        : "r"(a0), "r"(a1), "r"(a2), "r"(a3), "r"(b0), "r"(b1));
}

// One dual-matmul phase: D = X @ {Wa, Wb}^T for the warp's 16 j-cols of both
// mats (4 n-tiles). X[16][K] fp16 in smem (aaddr = base + (l&15)*stride +
// (l>>4)*16); B fragments from fragment-linear global via LDG.64. KT = K/16.
template <int KT, int OFFA, int OFFB>
__device__ __forceinline__ void mma_phase(const uint32_t* __restrict__ wb,
                                          uint32_t aaddr, float* cA0, float* cA1,
                                          float* cB0, float* cB1) {
#pragma unroll
    for (int q = 0; q < KT; ++q) {
        uint32_t a0, a1, a2, a3;
        ldsm4(aaddr + q * 32, a0, a1, a2, a3);
        uint2 bA0 = *reinterpret_cast<const uint2*>(wb + OFFA + q * 1024);
        uint2 bA1 = *reinterpret_cast<const uint2*>(wb + OFFA + q * 1024 + 64);
        uint2 bB0 = *reinterpret_cast<const uint2*>(wb + OFFB + q * 1024);
        uint2 bB1 = *reinterpret_cast<const uint2*>(wb + OFFB + q * 1024 + 64);
        mma16816(cA0, a0, a1, a2, a3, bA0.x, bA0.y);
        mma16816(cA1, a0, a1, a2, a3, bA1.x, bA1.y);
        mma16816(cB0, a0, a1, a2, a3, bB0.x, bB0.y);
        mma16816(cB1, a0, a1, a2, a3, bB1.x, bB1.y);
    }
}

// RK4 for one cell. C-frag lanes<16 own (batch = lane/4, 4 j slots); they run
// the fp32 elementwise update and store new h as fp16 pairs. bufs ping-pong;
// after 4 subs the final h is in bufs[cu] (cu net-unchanged).
template <int OFFG, int OFFR>
__device__ __forceinline__ void rk4_mma(const uint32_t* __restrict__ wb,
                                        const float* it, const float* xin,
                                        const float* xg, float* hst, char* buf0,
                                        char* buf1, const uint32_t aaddr[2],
                                        int& cu, bool act, int hoff) {
    float ka[4] = {0.f, 0.f, 0.f, 0.f};
    float ht[4] = {hst[0], hst[1], hst[2], hst[3]};
#pragma unroll
    for (int sub = 0; sub < 4; ++sub) {
        float cg0[4] = {0, 0, 0, 0}, cg1[4] = {0, 0, 0, 0};
        float cr0[4] = {0, 0, 0, 0}, cr1[4] = {0, 0, 0, 0};
        mma_phase<8, OFFG, OFFR>(wb, aaddr[cu], cg0, cg1, cr0, cr1);
        const float kw = (sub == 0 || sub == 3) ? 1.f : 2.f;
        const float cv = (sub < 2) ? 0.5f : 1.f;
        if (act) {
            float nh[4];
#pragma unroll
            for (int s4 = 0; s4 < 4; ++s4) {
                float ra = (s4 & 2) ? cg1[s4 & 1] : cg0[s4 & 1];
                float rb = (s4 & 2) ? cr1[s4 & 1] : cr0[s4 & 1];
                float gate = gate_fn(ra + xg[s4]);
                float kv = fmaf(gate, rb, fmaf(-ht[s4], it[s4], xin[s4]));
                ka[s4] = fmaf(kw, kv, ka[s4]);
                nh[s4] = (sub < 3) ? fmaf(cv, kv, hst[s4])
                                   : fast_tanh(fmaf(ka[s4], 0.16666667f, hst[s4]));
                ht[s4] = nh[s4];
            }
            char* dst = cu ? buf0 : buf1;  // next buffer = cu^1
            *reinterpret_cast<__half2*>(dst + hoff) = __floats2half2_rn(nh[0], nh[1]);
            *reinterpret_cast<__half2*>(dst + hoff + 16) =
                __floats2half2_rn(nh[2], nh[3]);
        }
        __syncthreads();
        cu ^= 1;
    }
    hst[0] = ht[0];
    hst[1] = ht[1];
    hst[2] = ht[2];
    hst[3] = ht[3];
}

// ---------------- persistent recurrence: 128 CTAs x 256 threads ----------------
// M=16 MMA tiles: rows 0-3 = real batches, rows 4-15 zero padding. Warp w owns
// j columns [w*16, w*16+16). Lane l<16 owns (batch l/4, j slots {w*16+2(l%4)
// +{0,1}, +8+{0,1}}) for the elementwise RK4 update.
__global__ void __launch_bounds__(256, 1)
ltc_recurrent(const float* __restrict__ seq, const float* __restrict__ ctx,
              const float* __restrict__ tau0, const float* __restrict__ bg0,
              const float* __restrict__ tau1, const float* __restrict__ bg1,
              const float* __restrict__ W1, const float* __restrict__ b1,
              const float* __restrict__ W2, const float* __restrict__ b2,
              float* __restrict__ out) {
    __shared__ __align__(16) __half hA[2][16 * 136];  // cell-0 h ping-pong, fp16
    __shared__ __align__(16) __half hB[2][16 * 136];  // cell-1 h ping-pong
    __shared__ __align__(16) __half xsm[2][16 * 72];  // x double buffer, fp16
    __shared__ __align__(16) float xcf[128];
    __shared__ __align__(16) float st0[512];
    const int tid = threadIdx.x, lane = tid & 31, w = tid >> 5;
    const int b0g = blockIdx.x * 4;
    const bool act = lane < 16;

    // zero all fp16 buffers (rows 4-15 stay zero forever = M padding)
    {
        __half z = __float2half(0.f);
        for (int i = tid; i < 2 * 16 * 136; i += 256) {
            reinterpret_cast<__half*>(hA)[i] = z;
            reinterpret_cast<__half*>(hB)[i] = z;
        }
        for (int i = tid; i < 2 * 16 * 72; i += 256)
            reinterpret_cast<__half*>(xsm)[i] = z;
    }
    if (tid < 128) xcf[tid] = ctx[(size_t)(b0g + (tid >> 5)) * 32 + (tid & 31)];
    __syncthreads();

    // per-lane slot parameters + step-invariant ctx projection (scalar, one-time)
    float xinc[4] = {0, 0, 0, 0}, xgc[4] = {0, 0, 0, 0};
    float it0s[4] = {1, 1, 1, 1}, it1s[4] = {1, 1, 1, 1}, bg1s[4] = {0, 0, 0, 0};
    int hoff = 0;
    if (act) {
        const int b = lane >> 2;
        hoff = b * HSTB + (w * 16 + 2 * (lane & 3)) * 2;
#pragma unroll
        for (int s4 = 0; s4 < 4; ++s4) {
            int j = w * 16 + ((s4 & 2) ? 8 : 0) + 2 * (lane & 3) + (s4 & 1);
            it0s[s4] = __fdividef(1.f, log1pf(__expf(tau0[j])) + 1.f);
            it1s[s4] = __fdividef(1.f, log1pf(__expf(tau1[j])) + 1.f);
            bg1s[s4] = bg1[j];
            float ai = 0.f, ag = 0.f;
            for (int k = 0; k < 32; ++k) {
                float xv = xcf[b * 32 + k];
                ai = fmaf(xv, __ldg(&g_Wc[j * 32 + k]), ai);
                ag = fmaf(xv, __ldg(&g_Wc[4096 + j * 32 + k]), ag);
            }
            xinc[s4] = ai;
            xgc[s4] = ag + bg0[j];
        }
    }

    // stage x(0) as fp16
    const int xb = tid >> 6, xk = tid & 63;
    const float* seqp = seq + ((size_t)(b0g + xb) * S_LEN) * 64 + xk;
    xsm[0][xb * 72 + xk] = __float2half(seqp[0]);
    __syncthreads();

    // ldmatrix A addresses: lane (l&15) -> row, (l>>4) -> 8-col half
    const uint32_t aoffh = (uint32_t)(lane & 15) * HSTB + (uint32_t)(lane >> 4) * 16;
    const uint32_t aoffx = (uint32_t)(lane & 15) * XSTB + (uint32_t)(lane >> 4) * 16;
    const uint32_t baseA = (uint32_t)__cvta_generic_to_shared(hA);
    const uint32_t baseB = (uint32_t)__cvta_generic_to_shared(hB);
    const uint32_t baseX = (uint32_t)__cvta_generic_to_shared(xsm);
    const uint32_t addr_hA[2] = {baseA + aoffh, baseA + 4352 + aoffh};
    const uint32_t addr_hB[2] = {baseB + aoffh, baseB + 4352 + aoffh};
    const uint32_t addr_x[2] = {baseX + aoffx, baseX + 2304 + aoffx};

    // warp's B-fragment base (n-tiles 2w, 2w+1 folded in; mats via imm offsets)
    const uint32_t* wb = g_Wm + (2 * w) * 64 + lane * 2;

    float hst0[4] = {0, 0, 0, 0}, hst1[4] = {0, 0, 0, 0};
    int cuA = 0, cuB = 0, p = 0;

    for (int s = 0; s < S_LEN; ++s) {
        // cell-0 input projections from x(s)
        float c0[4] = {0, 0, 0, 0}, c1[4] = {0, 0, 0, 0};
        float c2[4] = {0, 0, 0, 0}, c3[4] = {0, 0, 0, 0};
        mma_phase<4, MM_WIN0S, MM_WG0S>(wb, addr_x[p], c0, c1, c2, c3);
        float xin0[4], xg0[4];
#pragma unroll
        for (int s4 = 0; s4 < 4; ++s4) {
            xin0[s4] = ((s4 & 2) ? c1[s4 & 1] : c0[s4 & 1]) + xinc[s4];
            xg0[s4] = ((s4 & 2) ? c3[s4 & 1] : c2[s4 & 1]) + xgc[s4];
        }
        // cell 0 RK4 (final h0 in hA[cuA])
        rk4_mma<MM_WG0H, MM_WREC0>(wb, it0s, xin0, xg0, hst0, (char*)hA[0],
                                   (char*)hA[1], addr_hA, cuA, act, hoff);
        // stage x(s+1) (readers at next step; covered by cell-1's bars)
        if (s + 1 < S_LEN)
            xsm[p ^ 1][xb * 72 + xk] = __float2half(seqp[(size_t)(s + 1) * 64]);

        // cell-1 input projections from h0_new
        float d0[4] = {0, 0, 0, 0}, d1[4] = {0, 0, 0, 0};
        float d2[4] = {0, 0, 0, 0}, d3[4] = {0, 0, 0, 0};
        mma_phase<8, MM_WIN1, MM_WG1X>(wb, addr_hA[cuA], d0, d1, d2, d3);
        float xin1[4], xg1[4];
#pragma unroll
        for (int s4 = 0; s4 < 4; ++s4) {
            xin1[s4] = (s4 & 2) ? d1[s4 & 1] : d0[s4 & 1];
            xg1[s4] = ((s4 & 2) ? d3[s4 & 1] : d2[s4 & 1]) + bg1s[s4];
        }
        // cell 1 RK4
        rk4_mma<MM_WG1H, MM_WREC1>(wb, it1s, xin1, xg1, hst1, (char*)hB[0],
                                   (char*)hB[1], addr_hB, cuB, act, hoff);
        p ^= 1;
    }

    // ---- classifier: sigmoid(relu(h1 @ W1^T + b1) @ W2^T + b2) ----
    if (act) {
#pragma unroll
        for (int s4 = 0; s4 < 4; ++s4) {
            int j = w * 16 + ((s4 & 2) ? 8 : 0) + 2 * (lane & 3) + (s4 & 1);
            st0[(lane >> 2) * 128 + j] = hst1[s4];
        }
    }
    __syncthreads();
    if (tid < 128) {
        const int b = tid >> 5, ln = tid & 31;
        float a0 = b1[ln], a1 = b1[ln + 32];
        const float* hv = st0 + b * 128;
        const float* w0 = W1 + ln * 128;
        const float* w1 = W1 + (ln + 32) * 128;
#pragma unroll 8
        for (int k = 0; k < 128; ++k) {
            float h = hv[k];
            a0 = fmaf(h, w0[k], a0);
            a1 = fmaf(h, w1[k], a1);
        }
        a0 = fmaxf(a0, 0.f);
        a1 = fmaxf(a1, 0.f);
        float pr = a0 * __ldg(W2 + ln) + a1 * __ldg(W2 + ln + 32);
#pragma unroll
        for (int off = 16; off; off >>= 1)
            pr += __shfl_xor_sync(0xffffffffu, pr, off);
        if (ln == 0) out[b0g + b] = sigm(pr + b2[0]);
    }
}

extern "C" void kernel_launch(void* const* d_in, const int* in_sizes, int n_in,
                              void* d_out, int out_size) {
    const float* seq   = (const float*)d_in[0];
    const float* ctx   = (const float*)d_in[1];
    const float* tau0  = (const float*)d_in[2];
    const float* Win0  = (const float*)d_in[3];
    const float* Wrec0 = (const float*)d_in[4];
    const float* Wg0   = (const float*)d_in[5];
    const float* bg0   = (const float*)d_in[6];
    const float* tau1  = (const float*)d_in[7];
    const float* Win1  = (const float*)d_in[8];
    const float* Wrec1 = (const float*)d_in[9];
    const float* Wg1   = (const float*)d_in[10];
    const float* bg1   = (const float*)d_in[11];
    const float* W1    = (const float*)d_in[12];
    const float* b1    = (const float*)d_in[13];
    const float* W2    = (const float*)d_in[14];
    const float* b2    = (const float*)d_in[15];
    float* out = (float*)d_out;

    prep_weights<<<(MM_TOTAL + 8192 + 255) / 256, 256>>>(Win0, Wg0, Wrec0, Win1,
                                                         Wrec1, Wg1);
    ltc_recurrent<<<128, 256>>>(seq, ctx, tau0, bg0, tau1, bg1, W1, b1, W2, b2, out);
}

// round 13
// speedup vs baseline: 3.6828x; 1.1173x over previous
#include <cuda_runtime.h>
#include <cuda_fp16.h>
#include <cstdint>
#include <cstddef>

#define S_LEN 512

// mma-fragment-linear weights (u32 lane-regs). For mat,k-tile q,n-tile t:
// u32 at base + (q*16 + t)*64 + lane*2 + r holds halves {W[j][k0], W[j][k0+1]}
// with j = t*8 + lane/4, k0 = q*16 + r*8 + 2*(lane%4).
#define MM_WG0H  0
#define MM_WREC0 8192
#define MM_WIN1  16384
#define MM_WG1X  24576
#define MM_WG1H  32768
#define MM_WREC1 40960
#define MM_WIN0S 49152
#define MM_WG0S  53248
#define MM_TOTAL 57344

__device__ __align__(16) uint32_t g_Wm[MM_TOTAL];
// ctx mats fp32 row-major [j][32]: [0]=Win0 ctx part, [4096]=Wg0 ctx part
__device__ __align__(16) float g_Wc[2 * 4096];

#define HSTB 272  // h smem row stride bytes (136 halves)
#define XSTB 144  // x smem row stride bytes (72 halves)

__device__ __forceinline__ float sigm(float x) {
    return __fdividef(1.0f, 1.0f + __expf(-x));
}
__device__ __forceinline__ float fast_tanh(float x) {
    float ax = fabsf(x);
    float e = __expf(ax + ax);
    float t = 1.0f - __fdividef(2.0f, e + 1.0f);
    return copysignf(t, x);
}
// gate = sigmoid(tanh(z)); sigmoid of t in [-1,1] via degree-7 odd polynomial
__device__ __forceinline__ float gate_fn(float z) {
    float t = fast_tanh(z);
    float t2 = t * t;
    float p = fmaf(t2, -2.00134e-4f, 2.0833333e-3f);
    p = fmaf(t2, p, -2.0833334e-2f);
    p = fmaf(t2, p, 0.25f);
    return fmaf(t, p, 0.5f);
}

// ---------------- weight prep: fragment-linear fp16 + fp32 ctx ----------------
__global__ void __launch_bounds__(256) prep_weights(
    const float* __restrict__ Win0, const float* __restrict__ Wg0,
    const float* __restrict__ Wrec0, const float* __restrict__ Win1,
    const float* __restrict__ Wrec1, const float* __restrict__ Wg1) {
    int idx = blockIdx.x * 256 + threadIdx.x;
    if (idx < MM_TOTAL) {
        int mat, rem;
        if (idx < 49152) {
            mat = idx >> 13;
            rem = idx & 8191;
        } else {
            mat = 6 + ((idx - 49152) >> 12);
            rem = (idx - 49152) & 4095;
        }
        int q = rem >> 10;
        int rr = rem & 1023;
        int t = rr >> 6;
        int le = rr & 63;
        int l = le >> 1, r = le & 1;
        int j = t * 8 + (l >> 2);
        int k = q * 16 + (r << 3) + 2 * (l & 3);
        float f0, f1;
        switch (mat) {
            case 0: f0 = Wg0[j * 224 + 96 + k]; f1 = Wg0[j * 224 + 97 + k]; break;
            case 1: f0 = Wrec0[j * 128 + k]; f1 = Wrec0[j * 128 + k + 1]; break;
            case 2: f0 = Win1[j * 128 + k]; f1 = Win1[j * 128 + k + 1]; break;
            case 3: f0 = Wg1[j * 256 + k]; f1 = Wg1[j * 256 + k + 1]; break;
            case 4: f0 = Wg1[j * 256 + 128 + k]; f1 = Wg1[j * 256 + 129 + k]; break;
            case 5: f0 = Wrec1[j * 128 + k]; f1 = Wrec1[j * 128 + k + 1]; break;
            case 6: f0 = Win0[j * 96 + k]; f1 = Win0[j * 96 + k + 1]; break;
            default: f0 = Wg0[j * 224 + k]; f1 = Wg0[j * 224 + k + 1]; break;
        }
        uint32_t u = (uint32_t)__half_as_ushort(__float2half_rn(f0)) |
                     ((uint32_t)__half_as_ushort(__float2half_rn(f1)) << 16);
        g_Wm[idx] = u;
    } else if (idx < MM_TOTAL + 8192) {
        int r2 = idx - MM_TOTAL;
        int m = r2 >> 12, a = r2 & 4095;
        int j = a >> 5, k = a & 31;
        g_Wc[r2] = m ? Wg0[j * 224 + 64 + k] : Win0[j * 96 + 64 + k];
    }
}

// ---------------- mma primitives ----------------
__device__ __forceinline__ void ldsm4(uint32_t addr, uint32_t& r0, uint32_t& r1,
                                      uint32_t& r2, uint32_t& r3) {
    asm volatile("ldmatrix.sync.aligned.m8n8.x4.shared.b16 {%0,%1,%2,%3}, [%4];"
                 : "=r"(r0), "=r"(r1), "=r"(r2), "=r"(r3)
                 : "r"(addr));
}
__device__ __forceinline__ void mma16816(float* c, uint32_t a0, uint32_t a1,
                                         uint32_t a2, uint32_t a3, uint32_t b0,
                                         uint32_t b1) {
    asm volatile(
        "mma.sync.aligned.m16n8k16.row.col.f32.f16.f16.f32 "
        "{%0,%1,%2,%3}, {%4,%5,%6,%7}, {%8,%9}, {%0,%1,%2,%3};"
        : "+f"(c[0]), "+f"(c[1]), "+f"(c[2]), "+f"(c[3])
        : "r"(c[0] == c[0] ? a0 : a0), "r"(a1), "r"(a2), "r"(a3), "r"(b0), "r"(b1));
}

// Group dual-matmul phase: warp covers n-tiles [4*w4, 4*w4+4) of both mats
// (wb has the 4*w4 fold). X[16][K] fp16 in smem; B frags via LDG.64. KT = K/16.
template <int KT, int OFFA, int OFFB>
__device__ __forceinline__ void mma_phase_g(const uint32_t* __restrict__ wb,
                                            uint32_t aaddr, float cA[4][4],
                                            float cB[4][4]) {
#pragma unroll
    for (int q = 0; q < KT; ++q) {
        uint32_t a0, a1, a2, a3;
        ldsm4(aaddr + q * 32, a0, a1, a2, a3);
#pragma unroll
        for (int t = 0; t < 4; ++t) {
            uint2 bA = *reinterpret_cast<const uint2*>(wb + OFFA + (q * 16 + t) * 64);
            uint2 bB = *reinterpret_cast<const uint2*>(wb + OFFB + (q * 16 + t) * 64);
            mma16816(cA[t], a0, a1, a2, a3, bA.x, bA.y);
            mma16816(cB[t], a0, a1, a2, a3, bB.x, bB.y);
        }
    }
}

// RK4 for one cell run by ONE 128-thread group (named barrier BARID). Lanes<16
// own (batch=lane/4, 8 j slots: t*8 + 2*(lane%3)... t in 0..3, s2 in 0..1).
// nb0/nb1 = ping-pong buffers; hout (optional) also receives the final h.
template <int OFFG, int OFFR, int BARID>
__device__ __forceinline__ void rk4_g(const uint32_t* __restrict__ wb,
                                      const float* it, const float* xin,
                                      const float* xg, float* hst, char* nb0,
                                      char* nb1, const uint32_t aaddr[2], int& cu,
                                      bool act, int hoff, char* hout) {
    float ka[8] = {0, 0, 0, 0, 0, 0, 0, 0};
    float ht[8];
#pragma unroll
    for (int i = 0; i < 8; ++i) ht[i] = hst[i];
#pragma unroll
    for (int sub = 0; sub < 4; ++sub) {
        float cg[4][4] = {}, cr[4][4] = {};
        mma_phase_g<8, OFFG, OFFR>(wb, aaddr[cu], cg, cr);
        const float kw = (sub == 0 || sub == 3) ? 1.f : 2.f;
        const float cv = (sub < 2) ? 0.5f : 1.f;
        if (act) {
            char* dst = cu ? nb0 : nb1;  // next buffer = cu^1
#pragma unroll
            for (int t = 0; t < 4; ++t) {
                float nh2[2];
#pragma unroll
                for (int s2 = 0; s2 < 2; ++s2) {
                    const int i = t * 2 + s2;
                    float gate = gate_fn(cg[t][s2] + xg[i]);
                    float kv = fmaf(gate, cr[t][s2], fmaf(-ht[i], it[i], xin[i]));
                    ka[i] = fmaf(kw, kv, ka[i]);
                    float nh = (sub < 3)
                                   ? fmaf(cv, kv, hst[i])
                                   : fast_tanh(fmaf(ka[i], 0.16666667f, hst[i]));
                    ht[i] = nh;
                    nh2[s2] = nh;
                }
                __half2 hv = __floats2half2_rn(nh2[0], nh2[1]);
                *reinterpret_cast<__half2*>(dst + hoff + t * 16) = hv;
                if (sub == 3 && hout)
                    *reinterpret_cast<__half2*>(hout + hoff + t * 16) = hv;
            }
        }
        asm volatile("bar.sync %0, 128;" ::"r"(BARID) : "memory");
        cu ^= 1;
    }
#pragma unroll
    for (int i = 0; i < 8; ++i) hst[i] = ht[i];
}

// ---------------- persistent recurrence: 128 CTAs x 256 threads ----------------
// Warp-specialized cell pipeline: warps 0-3 (group A, bar 1) run the cell-0
// chain; warps 4-7 (group B, bar 2) run cell-1 one step behind, consuming h0
// via a parity double-buffer. One CTA __syncthreads per step couples them.
// Within a group, warp w4 owns j in [w4*32, w4*32+32) = n-tiles 4*w4..4*w4+3.
__global__ void __launch_bounds__(256, 1)
ltc_recurrent(const float* __restrict__ seq, const float* __restrict__ ctx,
              const float* __restrict__ tau0, const float* __restrict__ bg0,
              const float* __restrict__ tau1, const float* __restrict__ bg1,
              const float* __restrict__ W1, const float* __restrict__ b1,
              const float* __restrict__ W2, const float* __restrict__ b2,
              float* __restrict__ out) {
    __shared__ __align__(16) __half hA[2][16 * 136];   // cell-0 RK4 ping-pong
    __shared__ __align__(16) __half hB[2][16 * 136];   // cell-1 RK4 ping-pong
    __shared__ __align__(16) __half h0o[2][16 * 136];  // A->B handoff (parity)
    __shared__ __align__(16) __half xsm[2][16 * 72];   // x double buffer
    __shared__ __align__(16) float xcf[128];
    __shared__ __align__(16) float st0[512];
    const int tid = threadIdx.x, lane = tid & 31;
    const bool isA = tid < 128;
    const int w4 = (tid >> 5) & 3;
    const int b0g = blockIdx.x * 4;
    const bool act = lane < 16;

    // zero all fp16 A-operand buffers (rows 4-15 stay zero = M padding)
    {
        __half z = __float2half(0.f);
        for (int i = tid; i < 2 * 16 * 136; i += 256) {
            reinterpret_cast<__half*>(hA)[i] = z;
            reinterpret_cast<__half*>(hB)[i] = z;
            reinterpret_cast<__half*>(h0o)[i] = z;
        }
        for (int i = tid; i < 2 * 16 * 72; i += 256)
            reinterpret_cast<__half*>(xsm)[i] = z;
    }
    if (tid < 128) xcf[tid] = ctx[(size_t)(b0g + (tid >> 5)) * 32 + (tid & 31)];
    __syncthreads();

    // per-lane params: 8 slots i -> j = w4*32 + (i>>1)*8 + 2*(lane&3) + (i&1)
    float its[8], xinc[8] = {0, 0, 0, 0, 0, 0, 0, 0},
                  xgc[8] = {0, 0, 0, 0, 0, 0, 0, 0};
    int hoff = 0;
    if (act) {
        const int b = lane >> 2;
        hoff = b * HSTB + (w4 * 32 + 2 * (lane & 3)) * 2;
#pragma unroll
        for (int i = 0; i < 8; ++i) {
            int j = w4 * 32 + (i >> 1) * 8 + 2 * (lane & 3) + (i & 1);
            const float* taup = isA ? tau0 : tau1;
            its[i] = __fdividef(1.f, log1pf(__expf(taup[j])) + 1.f);
            if (isA) {
                float ai = 0.f, ag = 0.f;
                for (int k = 0; k < 32; ++k) {
                    float xv = xcf[b * 32 + k];
                    ai = fmaf(xv, __ldg(&g_Wc[j * 32 + k]), ai);
                    ag = fmaf(xv, __ldg(&g_Wc[4096 + j * 32 + k]), ag);
                }
                xinc[i] = ai;
                xgc[i] = ag + bg0[j];
            } else {
                xgc[i] = bg1[j];  // reuse xgc as bg1 bias for group B
            }
        }
    } else {
#pragma unroll
        for (int i = 0; i < 8; ++i) its[i] = 1.f;
    }

    // x staging: A thread j stages one half2: row xb = j>>5, feature pair j&31
    const int xb = tid >> 5;  // valid for A threads (tid<128)
    const int xk2 = tid & 31;
    const float* seqp = seq + ((size_t)(b0g + (xb & 3)) * S_LEN) * 64 + 2 * xk2;
    const int xoffb = (xb & 3) * XSTB + xk2 * 4;
    if (isA) {
        float2 v = *reinterpret_cast<const float2*>(seqp);
        *reinterpret_cast<__half2*>((char*)xsm + xoffb) = __floats2half2_rn(v.x, v.y);
    }
    __syncthreads();

    // ldmatrix A addresses
    const uint32_t aoffh = (uint32_t)(lane & 15) * HSTB + (uint32_t)(lane >> 4) * 16;
    const uint32_t aoffx = (uint32_t)(lane & 15) * XSTB + (uint32_t)(lane >> 4) * 16;
    const uint32_t bA0 = (uint32_t)__cvta_generic_to_shared(hA);
    const uint32_t bB0 = (uint32_t)__cvta_generic_to_shared(hB);
    const uint32_t bH0 = (uint32_t)__cvta_generic_to_shared(h0o);
    const uint32_t bX0 = (uint32_t)__cvta_generic_to_shared(xsm);
    const uint32_t addr_hA[2] = {bA0 + aoffh, bA0 + 4352 + aoffh};
    const uint32_t addr_hB[2] = {bB0 + aoffh, bB0 + 4352 + aoffh};
    const uint32_t addr_h0[2] = {bH0 + aoffh, bH0 + 4352 + aoffh};
    const uint32_t addr_x[2] = {bX0 + aoffx, bX0 + 2304 + aoffx};

    // warp's B-fragment base: n-tiles 4*w4.. folded; mats via template offsets
    const uint32_t* wb = g_Wm + w4 * 256 + lane * 2;

    float hst[8] = {0, 0, 0, 0, 0, 0, 0, 0};
    int cu = 0, p = 0;

    for (int s = 0; s <= S_LEN; ++s) {
        if (isA) {
            if (s < S_LEN) {
                // prefetch x(s+1)
                float2 xn = {0.f, 0.f};
                const bool hasn = (s + 1 < S_LEN);
                if (hasn)
                    xn = *reinterpret_cast<const float2*>(seqp + (size_t)(s + 1) * 64);
                // cell-0 input projections from x(s)
                float ci[4][4] = {}, cg[4][4] = {};
                mma_phase_g<4, MM_WIN0S, MM_WG0S>(wb, addr_x[p], ci, cg);
                float xin0[8], xg0[8];
#pragma unroll
                for (int i = 0; i < 8; ++i) {
                    xin0[i] = ci[i >> 1][i & 1] + xinc[i];
                    xg0[i] = cg[i >> 1][i & 1] + xgc[i];
                }
                // stage x(s+1) (readers: next step's A proj, after 4 bar-1s)
                if (hasn)
                    *reinterpret_cast<__half2*>((char*)xsm + (p ^ 1) * 2304 + xoffb) =
                        __floats2half2_rn(xn.x, xn.y);
                // cell-0 RK4; final h0 also published to h0o[s&1]
                rk4_g<MM_WG0H, MM_WREC0, 1>(wb, its, xin0, xg0, hst, (char*)hA[0],
                                            (char*)hA[1], addr_hA, cu, act, hoff,
                                            (char*)h0o[s & 1]);
                p ^= 1;
            }
        } else {
            if (s > 0) {
                // cell-1 input projections from h0(s-1)
                float ci[4][4] = {}, cg[4][4] = {};
                mma_phase_g<8, MM_WIN1, MM_WG1X>(wb, addr_h0[(s - 1) & 1], ci, cg);
                float xin1[8], xg1[8];
#pragma unroll
                for (int i = 0; i < 8; ++i) {
                    xin1[i] = ci[i >> 1][i & 1];
                    xg1[i] = cg[i >> 1][i & 1] + xgc[i];  // xgc = bg1 for B
                }
                // cell-1 RK4
                rk4_g<MM_WG1H, MM_WREC1, 2>(wb, its, xin1, xg1, hst, (char*)hB[0],
                                            (char*)hB[1], addr_hB, cu, act, hoff,
                                            nullptr);
            }
        }
        __syncthreads();
    }

    // ---- classifier: sigmoid(relu(h1 @ W1^T + b1) @ W2^T + b2) ----
    if (!isA && act) {
#pragma unroll
        for (int i = 0; i < 8; ++i) {
            int j = w4 * 32 + (i >> 1) * 8 + 2 * (lane & 3) + (i & 1);
            st0[(lane >> 2) * 128 + j] = hst[i];
        }
    }
    __syncthreads();
    if (tid < 128) {
        const int b = tid >> 5, ln = tid & 31;
        float a0 = b1[ln], a1 = b1[ln + 32];
        const float* hv = st0 + b * 128;
        const float* w0 = W1 + ln * 128;
        const float* w1 = W1 + (ln + 32) * 128;
#pragma unroll 8
        for (int k = 0; k < 128; ++k) {
            float h = hv[k];
            a0 = fmaf(h, w0[k], a0);
            a1 = fmaf(h, w1[k], a1);
        }
        a0 = fmaxf(a0, 0.f);
        a1 = fmaxf(a1, 0.f);
        float pr = a0 * __ldg(W2 + ln) + a1 * __ldg(W2 + ln + 32);
#pragma unroll
        for (int off = 16; off; off >>= 1)
            pr += __shfl_xor_sync(0xffffffffu, pr, off);
        if (ln == 0) out[b0g + b] = sigm(pr + b2[0]);
    }
}

extern "C" void kernel_launch(void* const* d_in, const int* in_sizes, int n_in,
                              void* d_out, int out_size) {
    const float* seq   = (const float*)d_in[0];
    const float* ctx   = (const float*)d_in[1];
    const float* tau0  = (const float*)d_in[2];
    const float* Win0  = (const float*)d_in[3];
    const float* Wrec0 = (const float*)d_in[4];
    const float* Wg0   = (const float*)d_in[5];
    const float* bg0   = (const float*)d_in[6];
    const float* tau1  = (const float*)d_in[7];
    const float* Win1  = (const float*)d_in[8];
    const float* Wrec1 = (const float*)d_in[9];
    const float* Wg1   = (const float*)d_in[10];
    const float* bg1   = (const float*)d_in[11];
    const float* W1    = (const float*)d_in[12];
    const float* b1    = (const float*)d_in[13];
    const float* W2    = (const float*)d_in[14];
    const float* b2    = (const float*)d_in[15];
    float* out = (float*)d_out;

    prep_weights<<<(MM_TOTAL + 8192 + 255) / 256, 256>>>(Win0, Wg0, Wrec0, Win1,
                                                         Wrec1, Wg1);
    ltc_recurrent<<<128, 256>>>(seq, ctx, tau0, bg0, tau1, bg1, W1, b1, W2, b2, out);
}

// round 14
// speedup vs baseline: 4.2507x; 1.1542x over previous
#include <cuda_runtime.h>
#include <cuda_fp16.h>
#include <cstdint>
#include <cstddef>

#define S_LEN 512

// mma-fragment-linear weights (u32 lane-regs). For mat,k-tile q,n-tile t:
// u32 at base + (q*16 + t)*64 + lane*2 + r holds halves {W[j][k0], W[j][k0+1]}
// with j = t*8 + lane/4, k0 = q*16 + r*8 + 2*(lane%4).
#define MM_WG0H  0
#define MM_WREC0 8192
#define MM_WIN1  16384
#define MM_WG1X  24576
#define MM_WG1H  32768
#define MM_WREC1 40960
#define MM_WIN0S 49152
#define MM_WG0S  53248
#define MM_TOTAL 57344

__device__ __align__(16) uint32_t g_Wm[MM_TOTAL];
// ctx mats fp32 row-major [j][32]: [0]=Win0 ctx part, [4096]=Wg0 ctx part
__device__ __align__(16) float g_Wc[2 * 4096];

#define HSTB 272  // h smem row stride bytes (136 halves)
#define XSTB 144  // x smem row stride bytes (72 halves)
#define DUPH (12 * HSTB)
#define DUPX (12 * XSTB)

__device__ __forceinline__ float sigm(float x) {
    return __fdividef(1.0f, 1.0f + __expf(-x));
}
__device__ __forceinline__ float fast_tanh(float x) {
    float ax = fabsf(x);
    float e = __expf(ax + ax);
    float t = 1.0f - __fdividef(2.0f, e + 1.0f);
    return copysignf(t, x);
}
// gate = sigmoid(tanh(z)); sigmoid of t in [-1,1] via degree-7 odd polynomial
__device__ __forceinline__ float gate_fn(float z) {
    float t = fast_tanh(z);
    float t2 = t * t;
    float p = fmaf(t2, -2.00134e-4f, 2.0833333e-3f);
    p = fmaf(t2, p, -2.0833334e-2f);
    p = fmaf(t2, p, 0.25f);
    return fmaf(t, p, 0.5f);
}

// ---------------- weight prep: fragment-linear fp16 + fp32 ctx ----------------
__global__ void __launch_bounds__(256) prep_weights(
    const float* __restrict__ Win0, const float* __restrict__ Wg0,
    const float* __restrict__ Wrec0, const float* __restrict__ Win1,
    const float* __restrict__ Wrec1, const float* __restrict__ Wg1) {
    int idx = blockIdx.x * 256 + threadIdx.x;
    if (idx < MM_TOTAL) {
        int mat, rem;
        if (idx < 49152) {
            mat = idx >> 13;
            rem = idx & 8191;
        } else {
            mat = 6 + ((idx - 49152) >> 12);
            rem = (idx - 49152) & 4095;
        }
        int q = rem >> 10;
        int rr = rem & 1023;
        int t = rr >> 6;
        int le = rr & 63;
        int l = le >> 1, r = le & 1;
        int j = t * 8 + (l >> 2);
        int k = q * 16 + (r << 3) + 2 * (l & 3);
        float f0, f1;
        switch (mat) {
            case 0: f0 = Wg0[j * 224 + 96 + k]; f1 = Wg0[j * 224 + 97 + k]; break;
            case 1: f0 = Wrec0[j * 128 + k]; f1 = Wrec0[j * 128 + k + 1]; break;
            case 2: f0 = Win1[j * 128 + k]; f1 = Win1[j * 128 + k + 1]; break;
            case 3: f0 = Wg1[j * 256 + k]; f1 = Wg1[j * 256 + k + 1]; break;
            case 4: f0 = Wg1[j * 256 + 128 + k]; f1 = Wg1[j * 256 + 129 + k]; break;
            case 5: f0 = Wrec1[j * 128 + k]; f1 = Wrec1[j * 128 + k + 1]; break;
            case 6: f0 = Win0[j * 96 + k]; f1 = Win0[j * 96 + k + 1]; break;
            default: f0 = Wg0[j * 224 + k]; f1 = Wg0[j * 224 + k + 1]; break;
        }
        uint32_t u = (uint32_t)__half_as_ushort(__float2half_rn(f0)) |
                     ((uint32_t)__half_as_ushort(__float2half_rn(f1)) << 16);
        g_Wm[idx] = u;
    } else if (idx < MM_TOTAL + 8192) {
        int r2 = idx - MM_TOTAL;
        int m = r2 >> 12, a = r2 & 4095;
        int j = a >> 5, k = a & 31;
        g_Wc[r2] = m ? Wg0[j * 224 + 64 + k] : Win0[j * 96 + 64 + k];
    }
}

// ---------------- mma primitives ----------------
__device__ __forceinline__ void ldsm4(uint32_t addr, uint32_t& r0, uint32_t& r1,
                                      uint32_t& r2, uint32_t& r3) {
    asm volatile("ldmatrix.sync.aligned.m8n8.x4.shared.b16 {%0,%1,%2,%3}, [%4];"
                 : "=r"(r0), "=r"(r1), "=r"(r2), "=r"(r3)
                 : "r"(addr));
}
__device__ __forceinline__ void mma16816(float* c, uint32_t a0, uint32_t a1,
                                         uint32_t a2, uint32_t a3, uint32_t b0,
                                         uint32_t b1) {
    asm volatile(
        "mma.sync.aligned.m16n8k16.row.col.f32.f16.f16.f32 "
        "{%0,%1,%2,%3}, {%4,%5,%6,%7}, {%8,%9}, {%0,%1,%2,%3};"
        : "+f"(c[0]), "+f"(c[1]), "+f"(c[2]), "+f"(c[3])
        : "r"(a0), "r"(a1), "r"(a2), "r"(a3), "r"(b0), "r"(b1));
}

// Group dual-matmul phase: warp covers n-tiles [4*w4, 4*w4+4) of both mats
// (wb has the 4*w4 fold). X[16][K] fp16 in smem; B frags via LDG.64. KT = K/16.
template <int KT, int OFFA, int OFFB>
__device__ __forceinline__ void mma_phase_g(const uint32_t* __restrict__ wb,
                                            uint32_t aaddr, float cA[4][4],
                                            float cB[4][4]) {
#pragma unroll
    for (int q = 0; q < KT; ++q) {
        uint32_t a0, a1, a2, a3;
        ldsm4(aaddr + q * 32, a0, a1, a2, a3);
#pragma unroll
        for (int t = 0; t < 4; ++t) {
            uint2 bA = *reinterpret_cast<const uint2*>(wb + OFFA + (q * 16 + t) * 64);
            uint2 bB = *reinterpret_cast<const uint2*>(wb + OFFB + (q * 16 + t) * 64);
            mma16816(cA[t], a0, a1, a2, a3, bA.x, bA.y);
            mma16816(cB[t], a0, a1, a2, a3, bB.x, bB.y);
        }
    }
}

// Extract this lane's slot value from the dual C-frags. A-operand rows 0-3 and
// 12-15 hold duplicated batches, so lanes 0-15 read c0/c1 of tiles 0,1 and
// lanes 16-31 read c2/c3 of tiles 2,3 — every lane gets 4 valid slots.
template <int TT, int S2>
__device__ __forceinline__ float csel(const float c[4][4], bool hi) {
    return hi ? c[2 + TT][2 + S2] : c[TT][S2];
}

// RK4 for one cell run by ONE 128-thread group (named barrier BARID). Every
// lane owns 4 (batch, j) slots; new h stored to row b and dup row 12+b.
template <int OFFG, int OFFR, int BARID>
__device__ __forceinline__ void rk4_g(const uint32_t* __restrict__ wb,
                                      const float* it, const float* xin,
                                      const float* xg, float* hst, char* nb0,
                                      char* nb1, const uint32_t aaddr[2], int& cu,
                                      bool hi, int hoff, char* hout) {
    float ka[4] = {0, 0, 0, 0};
    float ht[4] = {hst[0], hst[1], hst[2], hst[3]};
#pragma unroll
    for (int sub = 0; sub < 4; ++sub) {
        float cg[4][4] = {}, cr[4][4] = {};
        mma_phase_g<8, OFFG, OFFR>(wb, aaddr[cu], cg, cr);
        const float kw = (sub == 0 || sub == 3) ? 1.f : 2.f;
        const float cv = (sub < 2) ? 0.5f : 1.f;
        char* dst = cu ? nb0 : nb1;  // next buffer = cu^1
#pragma unroll
        for (int tt = 0; tt < 2; ++tt) {
            float nh2[2];
#pragma unroll
            for (int s2 = 0; s2 < 2; ++s2) {
                const int i = tt * 2 + s2;
                float ra = (s2 == 0) ? csel<0, 0>(cg, hi) : csel<0, 1>(cg, hi);
                float rb = (s2 == 0) ? csel<0, 0>(cr, hi) : csel<0, 1>(cr, hi);
                if (tt == 1) {
                    ra = (s2 == 0) ? csel<1, 0>(cg, hi) : csel<1, 1>(cg, hi);
                    rb = (s2 == 0) ? csel<1, 0>(cr, hi) : csel<1, 1>(cr, hi);
                }
                float gate = gate_fn(ra + xg[i]);
                float kv = fmaf(gate, rb, fmaf(-ht[i], it[i], xin[i]));
                ka[i] = fmaf(kw, kv, ka[i]);
                float nh = (sub < 3) ? fmaf(cv, kv, hst[i])
                                     : fast_tanh(fmaf(ka[i], 0.16666667f, hst[i]));
                ht[i] = nh;
                nh2[s2] = nh;
            }
            __half2 hv = __floats2half2_rn(nh2[0], nh2[1]);
            *reinterpret_cast<__half2*>(dst + hoff + tt * 16) = hv;
            *reinterpret_cast<__half2*>(dst + hoff + tt * 16 + DUPH) = hv;
            if (sub == 3 && hout) {
                *reinterpret_cast<__half2*>(hout + hoff + tt * 16) = hv;
                *reinterpret_cast<__half2*>(hout + hoff + tt * 16 + DUPH) = hv;
            }
        }
        asm volatile("bar.sync %0, 128;" ::"r"(BARID) : "memory");
        cu ^= 1;
    }
#pragma unroll
    for (int i = 0; i < 4; ++i) hst[i] = ht[i];
}

// ---------------- persistent recurrence: 128 CTAs x 256 threads ----------------
// Warp-specialized cell pipeline: warps 0-3 (group A, bar 1) run the cell-0
// chain; warps 4-7 (group B, bar 2) run cell-1 one step behind, consuming h0
// via a parity double-buffer. A-operand rows 0-3 and 12-15 duplicate the 4
// batches so all 32 lanes receive valid C fragments (4 slots each).
__global__ void __launch_bounds__(256, 1)
ltc_recurrent(const float* __restrict__ seq, const float* __restrict__ ctx,
              const float* __restrict__ tau0, const float* __restrict__ bg0,
              const float* __restrict__ tau1, const float* __restrict__ bg1,
              const float* __restrict__ W1, const float* __restrict__ b1,
              const float* __restrict__ W2, const float* __restrict__ b2,
              float* __restrict__ out) {
    __shared__ __align__(16) __half hA[2][16 * 136];   // cell-0 RK4 ping-pong
    __shared__ __align__(16) __half hB[2][16 * 136];   // cell-1 RK4 ping-pong
    __shared__ __align__(16) __half h0o[2][16 * 136];  // A->B handoff (parity)
    __shared__ __align__(16) __half xsm[2][16 * 72];   // x double buffer
    __shared__ __align__(16) float xcf[128];
    __shared__ __align__(16) float st0[512];
    const int tid = threadIdx.x, lane = tid & 31;
    const bool isA = tid < 128;
    const int w4 = (tid >> 5) & 3;
    const int b0g = blockIdx.x * 4;
    const bool hi = lane >= 16;
    const int base_t = hi ? 2 : 0;
    const int b = (lane & 15) >> 2;

    // zero all fp16 A-operand buffers (rows 4-11 stay zero = M padding)
    {
        __half z = __float2half(0.f);
        for (int i = tid; i < 2 * 16 * 136; i += 256) {
            reinterpret_cast<__half*>(hA)[i] = z;
            reinterpret_cast<__half*>(hB)[i] = z;
            reinterpret_cast<__half*>(h0o)[i] = z;
        }
        for (int i = tid; i < 2 * 16 * 72; i += 256)
            reinterpret_cast<__half*>(xsm)[i] = z;
    }
    if (tid < 128) xcf[tid] = ctx[(size_t)(b0g + (tid >> 5)) * 32 + (tid & 31)];
    __syncthreads();

    // per-lane params: 4 slots i -> j = w4*32 + (base_t + (i>>1))*8 +
    //                                  2*(lane&3) + (i&1), batch b
    float its[4], xinc[4] = {0, 0, 0, 0}, xgc[4] = {0, 0, 0, 0};
    const int hoff = b * HSTB + (w4 * 32 + base_t * 8 + 2 * (lane & 3)) * 2;
#pragma unroll
    for (int i = 0; i < 4; ++i) {
        int j = w4 * 32 + (base_t + (i >> 1)) * 8 + 2 * (lane & 3) + (i & 1);
        const float* taup = isA ? tau0 : tau1;
        its[i] = __fdividef(1.f, log1pf(__expf(taup[j])) + 1.f);
        if (isA) {
            float ai = 0.f, ag = 0.f;
            for (int k = 0; k < 32; ++k) {
                float xv = xcf[b * 32 + k];
                ai = fmaf(xv, __ldg(&g_Wc[j * 32 + k]), ai);
                ag = fmaf(xv, __ldg(&g_Wc[4096 + j * 32 + k]), ag);
            }
            xinc[i] = ai;
            xgc[i] = ag + bg0[j];
        } else {
            xgc[i] = bg1[j];  // xgc = bg1 bias for group B
        }
    }

    // x staging: A thread stages one half2 to row (xb&3) and its dup row +12
    const int xb = tid >> 5;
    const int xk2 = tid & 31;
    const float* seqp = seq + ((size_t)(b0g + (xb & 3)) * S_LEN) * 64 + 2 * xk2;
    const int xoffb = (xb & 3) * XSTB + xk2 * 4;
    if (isA) {
        float2 v = *reinterpret_cast<const float2*>(seqp);
        __half2 hv = __floats2half2_rn(v.x, v.y);
        *reinterpret_cast<__half2*>((char*)xsm + xoffb) = hv;
        *reinterpret_cast<__half2*>((char*)xsm + xoffb + DUPX) = hv;
    }
    __syncthreads();

    // ldmatrix A addresses
    const uint32_t aoffh = (uint32_t)(lane & 15) * HSTB + (uint32_t)(lane >> 4) * 16;
    const uint32_t aoffx = (uint32_t)(lane & 15) * XSTB + (uint32_t)(lane >> 4) * 16;
    const uint32_t bA0 = (uint32_t)__cvta_generic_to_shared(hA);
    const uint32_t bB0 = (uint32_t)__cvta_generic_to_shared(hB);
    const uint32_t bH0 = (uint32_t)__cvta_generic_to_shared(h0o);
    const uint32_t bX0 = (uint32_t)__cvta_generic_to_shared(xsm);
    const uint32_t addr_hA[2] = {bA0 + aoffh, bA0 + 4352 + aoffh};
    const uint32_t addr_hB[2] = {bB0 + aoffh, bB0 + 4352 + aoffh};
    const uint32_t addr_h0[2] = {bH0 + aoffh, bH0 + 4352 + aoffh};
    const uint32_t addr_x[2] = {bX0 + aoffx, bX0 + 2304 + aoffx};

    // warp's B-fragment base: n-tiles 4*w4.. folded; mats via template offsets
    const uint32_t* wb = g_Wm + w4 * 256 + lane * 2;

    float hst[4] = {0, 0, 0, 0};
    int cu = 0, p = 0;

    for (int s = 0; s <= S_LEN; ++s) {
        if (isA) {
            if (s < S_LEN) {
                // prefetch x(s+1)
                float2 xn = {0.f, 0.f};
                const bool hasn = (s + 1 < S_LEN);
                if (hasn)
                    xn = *reinterpret_cast<const float2*>(seqp + (size_t)(s + 1) * 64);
                // cell-0 input projections from x(s)
                float ci[4][4] = {}, cg[4][4] = {};
                mma_phase_g<4, MM_WIN0S, MM_WG0S>(wb, addr_x[p], ci, cg);
                float xin0[4], xg0[4];
                xin0[0] = csel<0, 0>(ci, hi) + xinc[0];
                xin0[1] = csel<0, 1>(ci, hi) + xinc[1];
                xin0[2] = csel<1, 0>(ci, hi) + xinc[2];
                xin0[3] = csel<1, 1>(ci, hi) + xinc[3];
                xg0[0] = csel<0, 0>(cg, hi) + xgc[0];
                xg0[1] = csel<0, 1>(cg, hi) + xgc[1];
                xg0[2] = csel<1, 0>(cg, hi) + xgc[2];
                xg0[3] = csel<1, 1>(cg, hi) + xgc[3];
                // stage x(s+1) (readers: next step's A proj, after 4 bar-1s)
                if (hasn) {
                    __half2 hv = __floats2half2_rn(xn.x, xn.y);
                    char* xd = (char*)xsm + (p ^ 1) * 2304 + xoffb;
                    *reinterpret_cast<__half2*>(xd) = hv;
                    *reinterpret_cast<__half2*>(xd + DUPX) = hv;
                }
                // cell-0 RK4; final h0 also published to h0o[s&1]
                rk4_g<MM_WG0H, MM_WREC0, 1>(wb, its, xin0, xg0, hst, (char*)hA[0],
                                            (char*)hA[1], addr_hA, cu, hi, hoff,
                                            (char*)h0o[s & 1]);
                p ^= 1;
            }
        } else {
            if (s > 0) {
                // cell-1 input projections from h0(s-1)
                float ci[4][4] = {}, cg[4][4] = {};
                mma_phase_g<8, MM_WIN1, MM_WG1X>(wb, addr_h0[(s - 1) & 1], ci, cg);
                float xin1[4], xg1[4];
                xin1[0] = csel<0, 0>(ci, hi);
                xin1[1] = csel<0, 1>(ci, hi);
                xin1[2] = csel<1, 0>(ci, hi);
                xin1[3] = csel<1, 1>(ci, hi);
                xg1[0] = csel<0, 0>(cg, hi) + xgc[0];
                xg1[1] = csel<0, 1>(cg, hi) + xgc[1];
                xg1[2] = csel<1, 0>(cg, hi) + xgc[2];
                xg1[3] = csel<1, 1>(cg, hi) + xgc[3];
                // cell-1 RK4
                rk4_g<MM_WG1H, MM_WREC1, 2>(wb, its, xin1, xg1, hst, (char*)hB[0],
                                            (char*)hB[1], addr_hB, cu, hi, hoff,
                                            nullptr);
            }
        }
        __syncthreads();
    }

    // ---- classifier: sigmoid(relu(h1 @ W1^T + b1) @ W2^T + b2) ----
    if (!isA) {
#pragma unroll
        for (int i = 0; i < 4; ++i) {
            int j = w4 * 32 + (base_t + (i >> 1)) * 8 + 2 * (lane & 3) + (i & 1);
            st0[b * 128 + j] = hst[i];
        }
    }
    __syncthreads();
    if (tid < 128) {
        const int bb = tid >> 5, ln = tid & 31;
        float a0 = b1[ln], a1 = b1[ln + 32];
        const float* hv = st0 + bb * 128;
        const float* w0 = W1 + ln * 128;
        const float* w1 = W1 + (ln + 32) * 128;
#pragma unroll 8
        for (int k = 0; k < 128; ++k) {
            float h = hv[k];
            a0 = fmaf(h, w0[k], a0);
            a1 = fmaf(h, w1[k], a1);
        }
        a0 = fmaxf(a0, 0.f);
        a1 = fmaxf(a1, 0.f);
        float pr = a0 * __ldg(W2 + ln) + a1 * __ldg(W2 + ln + 32);
#pragma unroll
        for (int off = 16; off; off >>= 1)
            pr += __shfl_xor_sync(0xffffffffu, pr, off);
        if (ln == 0) out[b0g + bb] = sigm(pr + b2[0]);
    }
}

extern "C" void kernel_launch(void* const* d_in, const int* in_sizes, int n_in,
                              void* d_out, int out_size) {
    const float* seq   = (const float*)d_in[0];
    const float* ctx   = (const float*)d_in[1];
    const float* tau0  = (const float*)d_in[2];
    const float* Win0  = (const float*)d_in[3];
    const float* Wrec0 = (const float*)d_in[4];
    const float* Wg0   = (const float*)d_in[5];
    const float* bg0   = (const float*)d_in[6];
    const float* tau1  = (const float*)d_in[7];
    const float* Win1  = (const float*)d_in[8];
    const float* Wrec1 = (const float*)d_in[9];
    const float* Wg1   = (const float*)d_in[10];
    const float* bg1   = (const float*)d_in[11];
    const float* W1    = (const float*)d_in[12];
    const float* b1    = (const float*)d_in[13];
    const float* W2    = (const float*)d_in[14];
    const float* b2    = (const float*)d_in[15];
    float* out = (float*)d_out;

    prep_weights<<<(MM_TOTAL + 8192 + 255) / 256, 256>>>(Win0, Wg0, Wrec0, Win1,
                                                         Wrec1, Wg1);
    ltc_recurrent<<<128, 256>>>(seq, ctx, tau0, bg0, tau1, bg1, W1, b1, W2, b2, out);
}